// round 3
// baseline (speedup 1.0000x reference)
#include <cuda_runtime.h>
#include <cuda_fp16.h>
#include <cstdint>

// ===================== problem constants =====================
constexpr int NTOK = 16384;     // 8*2048
constexpr int DDIM = 768;
constexpr int FDIM = 3072;
constexpr int NEXP = 8;
constexpr int CAP  = 2560;      // int(1.25*16384/8)

// ===================== device scratch (static; allocation-free) ==============
__device__ __half g_Xbuf[(size_t)NEXP * CAP * DDIM];   // [E][CAP][D] fp16
__device__ __half g_H   [(size_t)NEXP * CAP * FDIM];   // [E][CAP][F] fp16
__device__ __half g_w1t [(size_t)NEXP * FDIM * DDIM];  // [E][F][D] K-major fp16
__device__ __half g_w2t [(size_t)NEXP * DDIM * FDIM];  // [E][D][F] K-major fp16
__device__ int    g_route[NTOK];
__device__ float  g_prob [NTOK];
__device__ int    g_slot [NTOK];
__device__ int    g_tok  [NEXP * CAP];
__device__ int    g_cnt  [16];

// ===================== PTX helpers (sm_80-era, compute_103-safe) =============
__device__ __forceinline__ uint32_t smem_u32(const void* p) {
    uint32_t a;
    asm("{ .reg .u64 t; cvta.to.shared.u64 t, %1; cvt.u32.u64 %0, t; }"
        : "=r"(a) : "l"(p));
    return a;
}

#define CP_ASYNC16(dst_smem, src_gmem) \
    asm volatile("cp.async.cg.shared.global [%0], [%1], 16;" \
        :: "r"(dst_smem), "l"(src_gmem))
#define CP_COMMIT() asm volatile("cp.async.commit_group;" ::: "memory")
#define CP_WAIT(n)  asm volatile("cp.async.wait_group %0;" :: "n"(n) : "memory")

__device__ __forceinline__ void ldsm_x4(uint32_t& r0, uint32_t& r1,
                                        uint32_t& r2, uint32_t& r3, uint32_t addr) {
    asm volatile("ldmatrix.sync.aligned.m8n8.x4.shared.b16 {%0,%1,%2,%3}, [%4];"
        : "=r"(r0), "=r"(r1), "=r"(r2), "=r"(r3) : "r"(addr));
}

__device__ __forceinline__ void mma16816(float* d, const uint32_t* a, const uint32_t* b) {
    asm volatile(
        "mma.sync.aligned.m16n8k16.row.col.f32.f16.f16.f32 "
        "{%0,%1,%2,%3}, {%4,%5,%6,%7}, {%8,%9}, {%0,%1,%2,%3};"
        : "+f"(d[0]), "+f"(d[1]), "+f"(d[2]), "+f"(d[3])
        : "r"(a[0]), "r"(a[1]), "r"(a[2]), "r"(a[3]), "r"(b[0]), "r"(b[1]));
}

#define SMEM_SWIZZLE_128B(off) ((off) ^ (((off) >> 3) & 0x70))

// ===================== small kernels =====================
__global__ void zero_cnt_kernel() {
    if (threadIdx.x < 16) g_cnt[threadIdx.x] = 0;
}

// transpose [E][R][C] fp32 -> [E][C][R] fp16
__global__ void transpose_w1_kernel(const float* __restrict__ in) {
    __shared__ float tile[32][33];
    const int R = DDIM, C = FDIM;
    int e = blockIdx.z;
    int c0 = blockIdx.x * 32, r0 = blockIdx.y * 32;
    const float* inp = in + (size_t)e * R * C;
    __half* op = g_w1t + (size_t)e * R * C;
    int tx = threadIdx.x, ty = threadIdx.y;
#pragma unroll
    for (int k = 0; k < 32; k += 8)
        tile[ty + k][tx] = inp[(size_t)(r0 + ty + k) * C + c0 + tx];
    __syncthreads();
#pragma unroll
    for (int k = 0; k < 32; k += 8)
        op[(size_t)(c0 + ty + k) * R + r0 + tx] = __float2half(tile[tx][ty + k]);
}

__global__ void transpose_w2_kernel(const float* __restrict__ in) {
    __shared__ float tile[32][33];
    const int R = FDIM, C = DDIM;
    int e = blockIdx.z;
    int c0 = blockIdx.x * 32, r0 = blockIdx.y * 32;
    const float* inp = in + (size_t)e * R * C;
    __half* op = g_w2t + (size_t)e * R * C;
    int tx = threadIdx.x, ty = threadIdx.y;
#pragma unroll
    for (int k = 0; k < 32; k += 8)
        tile[ty + k][tx] = inp[(size_t)(r0 + ty + k) * C + c0 + tx];
    __syncthreads();
#pragma unroll
    for (int k = 0; k < 32; k += 8)
        op[(size_t)(c0 + ty + k) * R + r0 + tx] = __float2half(tile[tx][ty + k]);
}

// router: one warp per token; fp32 logits, argmax expert, softmax max-prob
__global__ void router_kernel(const float* __restrict__ x,
                              const float* __restrict__ sw,
                              const float* __restrict__ sb) {
    int t = (blockIdx.x * blockDim.x + threadIdx.x) >> 5;
    int lane = threadIdx.x & 31;
    if (t >= NTOK) return;
    const float* xr = x + (size_t)t * DDIM;
    float acc[8];
#pragma unroll
    for (int e = 0; e < 8; e++) acc[e] = 0.f;
    for (int d = lane; d < DDIM; d += 32) {
        float xv = xr[d];
        const float4* wr = (const float4*)(sw + (size_t)d * 8);
        float4 w0 = wr[0], w1 = wr[1];
        acc[0] += xv * w0.x; acc[1] += xv * w0.y;
        acc[2] += xv * w0.z; acc[3] += xv * w0.w;
        acc[4] += xv * w1.x; acc[5] += xv * w1.y;
        acc[6] += xv * w1.z; acc[7] += xv * w1.w;
    }
#pragma unroll
    for (int off = 16; off; off >>= 1)
#pragma unroll
        for (int e = 0; e < 8; e++)
            acc[e] += __shfl_xor_sync(0xFFFFFFFFu, acc[e], off);
    if (lane == 0) {
        float l[8];
        float best = -1e30f; int be = 0;
#pragma unroll
        for (int e = 0; e < 8; e++) {
            l[e] = acc[e] + sb[e];
            if (l[e] > best) { best = l[e]; be = e; }
        }
        float s = 0.f;
#pragma unroll
        for (int e = 0; e < 8; e++) s += expf(l[e] - best);
        float p = 1.0f / s;
        g_route[t] = be;
        g_prob[t] = p;
        int slot = atomicAdd(&g_cnt[be], 1);
        g_slot[t] = slot;
        if (slot < CAP) g_tok[be * CAP + slot] = t;
    }
}

// gather: one block per token; fp32 -> fp16 into expert buffer
__global__ void gather_kernel(const float* __restrict__ x) {
    int t = blockIdx.x;
    int e = g_route[t];
    int s = g_slot[t];
    if (s >= CAP) return;
    const float* src = x + (size_t)t * DDIM;
    __half* dst = g_Xbuf + ((size_t)e * CAP + s) * DDIM;
    for (int i = threadIdx.x; i < DDIM; i += blockDim.x)
        dst[i] = __float2half(src[i]);
}

// passthrough for dropped tokens (expected: none at these stats)
__global__ void passthru_kernel(const float* __restrict__ x, float* __restrict__ out) {
    int t = blockIdx.x * blockDim.x + threadIdx.x;
    if (t >= NTOK) return;
    if (g_slot[t] < CAP) return;
    float p = g_prob[t];
    const float* src = x + (size_t)t * DDIM;
    float* dst = out + (size_t)t * DDIM;
    for (int i = 0; i < DDIM; i++) dst[i] = src[i] * p;
}

// ===================== GEMM core =====================
// CTA tile 128x128, K-chunk 64, 256 threads = 8 warps in 4(M) x 2(N).
// smem: A bufs @ 0 / 16K, B bufs @ 32K / 48K. 64KB total.
__device__ __forceinline__ void issue_chunk(const __half* Ak, const __half* Bk,
                                            int ld, uint32_t sb, int buf, int tid) {
    uint32_t abase = sb + buf * 16384;
    uint32_t bbase = sb + 32768 + buf * 16384;
#pragma unroll
    for (int it = 0; it < 8; ++it) {
        int u = it * 256 + tid;
        int v = u & 1023;
        int row = v >> 3, seg = v & 7;
        const void* src = (const char*)((u < 1024 ? Ak : Bk) + (size_t)row * ld) + seg * 16;
        uint32_t dst = (u < 1024 ? abase : bbase) + SMEM_SWIZZLE_128B(row * 128 + seg * 16);
        CP_ASYNC16(dst, src);
    }
}

__device__ __forceinline__ void compute_chunk(uint32_t abase, uint32_t bbase,
                                              int wm, int wn, int lane,
                                              float acc[2][8][4]) {
#pragma unroll
    for (int ks = 0; ks < 4; ++ks) {
        uint32_t af[2][4];
#pragma unroll
        for (int mt = 0; mt < 2; ++mt) {
            int row = wm * 32 + mt * 16 + (lane & 15);
            int colb = ks * 32 + (lane >> 4) * 16;
            ldsm_x4(af[mt][0], af[mt][1], af[mt][2], af[mt][3],
                    abase + SMEM_SWIZZLE_128B(row * 128 + colb));
        }
        uint32_t bf[8][2];
#pragma unroll
        for (int np = 0; np < 4; ++np) {
            int nrow = wn * 64 + np * 16 + (lane >> 4) * 8 + (lane & 7);
            int colb = ks * 32 + ((lane >> 3) & 1) * 16;
            uint32_t r0, r1, r2, r3;
            ldsm_x4(r0, r1, r2, r3, bbase + SMEM_SWIZZLE_128B(nrow * 128 + colb));
            bf[np * 2][0] = r0;     bf[np * 2][1] = r1;
            bf[np * 2 + 1][0] = r2; bf[np * 2 + 1][1] = r3;
        }
#pragma unroll
        for (int mt = 0; mt < 2; ++mt)
#pragma unroll
            for (int nt = 0; nt < 8; ++nt)
                mma16816(acc[mt][nt], af[mt], bf[nt]);
    }
}

__device__ __forceinline__ void gemm_mainloop(int nk, const __half* Ab, const __half* Bb,
                                              int ld, uint32_t sb, int tid,
                                              int wm, int wn, int lane,
                                              float acc[2][8][4]) {
    issue_chunk(Ab, Bb, ld, sb, 0, tid);
    CP_COMMIT();
    for (int kc = 0; kc < nk; ++kc) {
        if (kc + 1 < nk) {
            issue_chunk(Ab + (kc + 1) * 64, Bb + (kc + 1) * 64, ld, sb, (kc + 1) & 1, tid);
            CP_COMMIT();
            CP_WAIT(1);
        } else {
            CP_WAIT(0);
        }
        __syncthreads();
        compute_chunk(sb + (kc & 1) * 16384, sb + 32768 + (kc & 1) * 16384,
                      wm, wn, lane, acc);
        __syncthreads();
    }
}

__device__ __forceinline__ float gelu_exact(float v) {
    return 0.5f * v * (1.0f + erff(v * 0.70710678118654752f));
}

// ===================== GEMM1: H = gelu(Xbuf @ w1t^T + b1) =====================
// grid: (FDIM/128=24, CAP/128=20, E=8)
__global__ void __launch_bounds__(256) gemm1_kernel(const float* __restrict__ b1) {
    extern __shared__ char smem[];
    uint32_t sb = smem_u32(smem);
    int tid = threadIdx.x, lane = tid & 31, w = tid >> 5;
    int wm = w & 3, wn = w >> 2;
    int e = blockIdx.z, m0 = blockIdx.y * 128, f0 = blockIdx.x * 128;
    int cnt = g_cnt[e];
    int mcnt = cnt < CAP ? cnt : CAP;
    if (m0 >= mcnt) return;

    float acc[2][8][4];
#pragma unroll
    for (int a = 0; a < 2; a++)
#pragma unroll
        for (int b = 0; b < 8; b++)
#pragma unroll
            for (int c = 0; c < 4; c++) acc[a][b][c] = 0.f;

    const __half* Ab = g_Xbuf + ((size_t)e * CAP + m0) * DDIM;
    const __half* Bb = g_w1t + (size_t)e * FDIM * DDIM + (size_t)f0 * DDIM;
    gemm_mainloop(DDIM / 64, Ab, Bb, DDIM, sb, tid, wm, wn, lane, acc);

    // epilogue: + bias, exact GELU, fp16 store
    const float* bb = b1 + (size_t)e * FDIM + f0 + wn * 64;
    __half* Hb = g_H + ((size_t)e * CAP + m0) * FDIM + f0;
    int lq = lane >> 2, lr = lane & 3;
#pragma unroll
    for (int nt = 0; nt < 8; ++nt) {
        float bc0 = bb[nt * 8 + lr * 2];
        float bc1 = bb[nt * 8 + lr * 2 + 1];
        int col = wn * 64 + nt * 8 + lr * 2;
#pragma unroll
        for (int mt = 0; mt < 2; ++mt) {
            int r0 = wm * 32 + mt * 16 + lq;
            __half2 v0 = __floats2half2_rn(gelu_exact(acc[mt][nt][0] + bc0),
                                           gelu_exact(acc[mt][nt][1] + bc1));
            __half2 v1 = __floats2half2_rn(gelu_exact(acc[mt][nt][2] + bc0),
                                           gelu_exact(acc[mt][nt][3] + bc1));
            *(__half2*)(Hb + (size_t)r0 * FDIM + col) = v0;
            *(__half2*)(Hb + (size_t)(r0 + 8) * FDIM + col) = v1;
        }
    }
}

// ===================== GEMM2: out[token] = (H @ w2t^T + b2) * prob ============
// grid: (DDIM/128=6, CAP/128=20, E=8)
__global__ void __launch_bounds__(256) gemm2_kernel(const float* __restrict__ b2,
                                                    float* __restrict__ out) {
    extern __shared__ char smem[];
    uint32_t sb = smem_u32(smem);
    int tid = threadIdx.x, lane = tid & 31, w = tid >> 5;
    int wm = w & 3, wn = w >> 2;
    int e = blockIdx.z, m0 = blockIdx.y * 128, n0 = blockIdx.x * 128;
    int cnt = g_cnt[e];
    int mcnt = cnt < CAP ? cnt : CAP;
    if (m0 >= mcnt) return;

    float acc[2][8][4];
#pragma unroll
    for (int a = 0; a < 2; a++)
#pragma unroll
        for (int b = 0; b < 8; b++)
#pragma unroll
            for (int c = 0; c < 4; c++) acc[a][b][c] = 0.f;

    const __half* Ab = g_H + ((size_t)e * CAP + m0) * FDIM;
    const __half* Bb = g_w2t + (size_t)e * DDIM * FDIM + (size_t)n0 * FDIM;
    gemm_mainloop(FDIM / 64, Ab, Bb, FDIM, sb, tid, wm, wn, lane, acc);

    // epilogue: + bias, * prob, scatter rows to tokens
    const float* bb = b2 + (size_t)e * DDIM + n0 + wn * 64;
    int lq = lane >> 2, lr = lane & 3;
    float bc0[8], bc1[8];
#pragma unroll
    for (int nt = 0; nt < 8; ++nt) {
        bc0[nt] = bb[nt * 8 + lr * 2];
        bc1[nt] = bb[nt * 8 + lr * 2 + 1];
    }
#pragma unroll
    for (int mt = 0; mt < 2; ++mt) {
#pragma unroll
        for (int half = 0; half < 2; ++half) {
            int row = wm * 32 + mt * 16 + lq + half * 8;
            int gm = m0 + row;
            if (gm < mcnt) {
                int tok = g_tok[e * CAP + gm];
                float p = g_prob[tok];
                float* orow = out + (size_t)tok * DDIM + n0 + wn * 64;
#pragma unroll
                for (int nt = 0; nt < 8; ++nt) {
                    float2 v;
                    v.x = (acc[mt][nt][half * 2]     + bc0[nt]) * p;
                    v.y = (acc[mt][nt][half * 2 + 1] + bc1[nt]) * p;
                    *(float2*)(orow + nt * 8 + lr * 2) = v;
                }
            }
        }
    }
}

// ===================== launch =====================
extern "C" void kernel_launch(void* const* d_in, const int* in_sizes, int n_in,
                              void* d_out, int out_size) {
    const float* x   = (const float*)d_in[0];
    const float* sw  = (const float*)d_in[1];
    const float* sbv = (const float*)d_in[2];
    const float* w1  = (const float*)d_in[3];
    const float* b1  = (const float*)d_in[4];
    const float* w2  = (const float*)d_in[5];
    const float* b2  = (const float*)d_in[6];
    float* out = (float*)d_out;

    const int SMEM_BYTES = 65536;
    cudaFuncSetAttribute(gemm1_kernel, cudaFuncAttributeMaxDynamicSharedMemorySize, SMEM_BYTES);
    cudaFuncSetAttribute(gemm2_kernel, cudaFuncAttributeMaxDynamicSharedMemorySize, SMEM_BYTES);

    zero_cnt_kernel<<<1, 32>>>();
    transpose_w1_kernel<<<dim3(FDIM / 32, DDIM / 32, NEXP), dim3(32, 8)>>>(w1);
    transpose_w2_kernel<<<dim3(DDIM / 32, FDIM / 32, NEXP), dim3(32, 8)>>>(w2);
    router_kernel<<<NTOK / 8, 256>>>(x, sw, sbv);
    gather_kernel<<<NTOK, 256>>>(x);
    gemm1_kernel<<<dim3(FDIM / 128, CAP / 128, NEXP), 256, SMEM_BYTES>>>(b1);
    gemm2_kernel<<<dim3(DDIM / 128, CAP / 128, NEXP), 256, SMEM_BYTES>>>(b2, out);
    passthru_kernel<<<(NTOK + 255) / 256, 256>>>(x, out);
}